// round 13
// baseline (speedup 1.0000x reference)
#include <cuda_runtime.h>
#include <cuda_bf16.h>
#include <math.h>
#include <stdint.h>

typedef __nv_bfloat16 bf16;

#define NN   10000
#define EE   160000
#define ETOT 170000   // EE + NN self loops
#define FIN  128
#define HID  512
#define HH   8
#define CC   64
#define NCLS 10
#define CAP  128      // per-node in-edge bucket capacity (P(overflow) ~ 1e-60)

// ---------------- scratch (device globals; no allocs allowed) ----------------
__device__ bf16  g_hb[NN * HID];          // bf16 h (GEMM A input + final input)
__device__ bf16  g_xb[NN * FIN];          // bf16 x
__device__ bf16  g_xlb[NN * HID];         // bf16 xl
__device__ bf16  g_xrb[NN * HID];         // bf16 xr
__device__ bf16  g_wbT[HID * FIN];        // Wb^T  [n][k]
__device__ bf16  g_wlT[3 * HID * HID];    // Wl^T per layer
__device__ bf16  g_wrT[3 * HID * HID];    // Wr^T per layer
__device__ int   g_cnt[NN];
__device__ int   g_bsrc[(size_t)NN * CAP];
__device__ float g_bdist[(size_t)NN * CAP];

// ---------------- fused: convert x to bf16 AND zero g_cnt -------------------
__global__ void conv_x_zero(const float* __restrict__ x)
{
    int i = blockIdx.x * blockDim.x + threadIdx.x;
    if (i < NN * FIN) g_xb[i] = __float2bfloat16(x[i]);
    if (i < NN) g_cnt[i] = 0;
}

// batched transpose+convert for all 7 weight matrices:
// z=0..2: Wl[z] (512x512), z=3..5: Wr[z-3], z=6: Wb (128x512, y<4 only)
__global__ void transp_bf16_batch7(const float* __restrict__ Wl,
                                   const float* __restrict__ Wr,
                                   const float* __restrict__ Wb)
{
    __shared__ float tile[32][33];
    int z = blockIdx.z;
    const float* src;
    bf16* dst;
    int K;
    if (z < 3)      { src = Wl + (size_t)z * HID * HID;       dst = g_wlT + (size_t)z * HID * HID;       K = HID; }
    else if (z < 6) { src = Wr + (size_t)(z - 3) * HID * HID; dst = g_wrT + (size_t)(z - 3) * HID * HID; K = HID; }
    else            { src = Wb;                               dst = g_wbT;                               K = FIN;
                      if (blockIdx.y >= FIN / 32) return; }
    int k0 = blockIdx.y * 32, n0 = blockIdx.x * 32;
    int tx = threadIdx.x, ty = threadIdx.y;   // 32 x 8
#pragma unroll
    for (int i = 0; i < 32; i += 8)
        tile[ty + i][tx] = src[(size_t)(k0 + ty + i) * HID + n0 + tx];
    __syncthreads();
#pragma unroll
    for (int i = 0; i < 32; i += 8)
        dst[(size_t)(n0 + ty + i) * K + k0 + tx] = __float2bfloat16(tile[tx][ty + i]);
}

// ---------------- bucket build ----------------------------------------------
__global__ void bucket_kernel(const int* __restrict__ ei,
                              const float* __restrict__ dist)
{
    int e = blockIdx.x * blockDim.x + threadIdx.x;
    if (e >= ETOT) return;
    int s, d; float dv;
    if (e < EE) { s = ei[e]; d = ei[EE + e]; dv = dist[e]; }
    else        { s = d = e - EE; dv = 0.f; }
    int pos = atomicAdd(&g_cnt[d], 1);
    if (pos < CAP) {
        g_bsrc [(size_t)d * CAP + pos] = s;
        g_bdist[(size_t)d * CAP + pos] = dv;
    }
}

// ---------------- bf16 tensor-core GEMM -------------------------------------
// Cb[M,N] = bf16(A[M,K] @ B^T + bias [elu]), B stored [N][K] bf16.
// CTA tile 128(M)x64(N), 256 thr, warp tile 32x32 (acc=32 regs -> occ 3),
// K-chunk 32, 3-stage cp.async ring, ldmatrix fragments.
__device__ __forceinline__ void mma_bf16(float* c, const uint32_t* a, const uint32_t* b)
{
    asm volatile(
        "mma.sync.aligned.m16n8k16.row.col.f32.bf16.bf16.f32 "
        "{%0,%1,%2,%3}, {%4,%5,%6,%7}, {%8,%9}, {%0,%1,%2,%3};"
        : "+f"(c[0]), "+f"(c[1]), "+f"(c[2]), "+f"(c[3])
        : "r"(a[0]), "r"(a[1]), "r"(a[2]), "r"(a[3]), "r"(b[0]), "r"(b[1]));
}
__device__ __forceinline__ void cp16(uint32_t dst, const void* src)
{
    asm volatile("cp.async.cg.shared.global [%0], [%1], 16;" :: "r"(dst), "l"(src));
}
__device__ __forceinline__ void ldsm4(uint32_t* r, uint32_t addr)
{
    asm volatile("ldmatrix.sync.aligned.m8n8.x4.shared.b16 {%0,%1,%2,%3}, [%4];"
                 : "=r"(r[0]), "=r"(r[1]), "=r"(r[2]), "=r"(r[3]) : "r"(addr));
}

#define A_BYTES     10240                  // 128 rows x 80B
#define B_BYTES     5120                   // 64 rows x 80B
#define STAGE_BYTES (A_BYTES + B_BYTES)    // 15360
#define GEMM_SMEM   (3 * STAGE_BYTES)      // 46080 (occ 3: 138KB/SM)
#define TILE_N      64

__global__ void __launch_bounds__(256, 3)
bf16gemm(const bf16* __restrict__ A,
         const bf16* __restrict__ B0, const bf16* __restrict__ B1,
         const float* __restrict__ bias0, const float* __restrict__ bias1,
         bf16* __restrict__ Cb0, bf16* __restrict__ Cb1,
         int M, int K, int doElu)
{
    extern __shared__ __align__(16) unsigned char smem[];
    const int N = HID;

    const int tid  = threadIdx.x;
    const int wid  = tid >> 5;
    const int lane = tid & 31;
    const int g    = lane >> 2;
    const int tg   = lane & 3;

    const bf16* B = B0;
    bf16* Cb = Cb0;
    const float* bi = bias0;
    int bx = blockIdx.x;
    if (B1 != nullptr && bx >= ((int)gridDim.x >> 1)) {
        B = B1; Cb = Cb1; bi = bias1; bx -= (int)gridDim.x >> 1;
    }
    const int m0 = blockIdx.y * 128;
    const int n0 = bx * TILE_N;
    const int warpM = (wid >> 1) * 32;     // 4 warps in M
    const int warpN = (wid & 1) * 32;      // 2 warps in N

    const uint32_t sbase = (uint32_t)__cvta_generic_to_shared(smem);

    const int lrow = tid >> 2;             // cp.async: row, quad
    const int lq   = tid & 3;

    // ldmatrix per-lane offsets within a stage
    uint32_t aOff[2];
#pragma unroll
    for (int mt = 0; mt < 2; mt++)
        aOff[mt] = (uint32_t)((warpM + mt * 16 + (lane & 15)) * 80 + (lane >> 4) * 16);
    uint32_t bOff[2];
#pragma unroll
    for (int np = 0; np < 2; np++)
        bOff[np] = (uint32_t)(A_BYTES +
                   (warpN + np * 16 + (lane & 7) + ((lane & 16) ? 8 : 0)) * 80 +
                   ((lane >> 3) & 1) * 16);

    float acc[2][4][4];
#pragma unroll
    for (int mt = 0; mt < 2; mt++)
#pragma unroll
        for (int nt = 0; nt < 4; nt++)
#pragma unroll
            for (int i = 0; i < 4; i++) acc[mt][nt][i] = 0.f;

    const int nStages = K >> 5;

    auto issue = [&](int buf, int ks) {
        uint32_t sA = sbase + buf * STAGE_BYTES;
        uint32_t sB = sA + A_BYTES;
        int k0 = ks << 5;
        // A: 128 rows x 4 quads = 512 quads / 256 thr = 2 each
#pragma unroll
        for (int i = 0; i < 2; i++) {
            int row = lrow + i * 64;
            int ar = m0 + row; if (ar >= M) ar = M - 1;
            cp16(sA + row * 80 + lq * 16, A + (size_t)ar * K + k0 + lq * 8);
        }
        // B: 64 rows x 4 quads = 256 quads / 256 thr = 1 each
        cp16(sB + lrow * 80 + lq * 16, B + (size_t)(n0 + (lrow & 63)) * K + k0 + lq * 8);
        asm volatile("cp.async.commit_group;");
    };

    issue(0, 0);
    if (nStages > 1) issue(1, 1);
    if (nStages > 2) issue(2, 2);

    for (int ks = 0; ks < nStages; ks++) {
        int rem = nStages - 1 - ks;
        if (rem >= 2)      asm volatile("cp.async.wait_group 2;");
        else if (rem == 1) asm volatile("cp.async.wait_group 1;");
        else               asm volatile("cp.async.wait_group 0;");
        __syncthreads();

        const uint32_t stage = sbase + (ks % 3) * STAGE_BYTES;

#pragma unroll
        for (int kk = 0; kk < 32; kk += 16) {
            const uint32_t kb = (kk >> 1) * 4;
            uint32_t a[2][4], b[2][4];
#pragma unroll
            for (int mt = 0; mt < 2; mt++)
                ldsm4(a[mt], stage + aOff[mt] + kb);
#pragma unroll
            for (int np = 0; np < 2; np++)
                ldsm4(b[np], stage + bOff[np] + kb);
#pragma unroll
            for (int mt = 0; mt < 2; mt++) {
                mma_bf16(acc[mt][0], a[mt], &b[0][0]);
                mma_bf16(acc[mt][1], a[mt], &b[0][2]);
                mma_bf16(acc[mt][2], a[mt], &b[1][0]);
                mma_bf16(acc[mt][3], a[mt], &b[1][2]);
            }
        }

        if (ks + 3 < nStages) issue((ks + 3) % 3, ks + 3);
    }

#pragma unroll
    for (int mt = 0; mt < 2; mt++) {
        int row0 = m0 + warpM + mt * 16 + g;
        int row1 = row0 + 8;
#pragma unroll
        for (int nt = 0; nt < 4; nt++) {
            int col = n0 + warpN + nt * 8 + tg * 2;
            float bx0 = bi[col], bx1 = bi[col + 1];
            float v0 = acc[mt][nt][0] + bx0;
            float v1 = acc[mt][nt][1] + bx1;
            float v2 = acc[mt][nt][2] + bx0;
            float v3 = acc[mt][nt][3] + bx1;
            if (doElu) {
                v0 = v0 > 0.f ? v0 : expm1f(v0);
                v1 = v1 > 0.f ? v1 : expm1f(v1);
                v2 = v2 > 0.f ? v2 : expm1f(v2);
                v3 = v3 > 0.f ? v3 : expm1f(v3);
            }
            if (row0 < M)
                *(__nv_bfloat162*)(Cb + (size_t)row0 * N + col) =
                    __nv_bfloat162(__float2bfloat16(v0), __float2bfloat16(v1));
            if (row1 < M)
                *(__nv_bfloat162*)(Cb + (size_t)row1 * N + col) =
                    __nv_bfloat162(__float2bfloat16(v2), __float2bfloat16(v3));
        }
    }
}

// ---------------- fused edge kernel: single pass, bf16, data-prefetch -------
__global__ void __launch_bounds__(256)
edge_fused(const float* __restrict__ We, const float* __restrict__ att,
           const float* __restrict__ bias)
{
    __shared__ float4 sWe[HID / 4];
    __shared__ float4 sAtt[HID / 4];

    for (int i = threadIdx.x; i < HID / 4; i += blockDim.x) {
        sWe[i]  = ((const float4*)We)[i];
        sAtt[i] = ((const float4*)att)[i];
    }
    __syncthreads();

    const int wid  = threadIdx.x >> 5;
    const int lane = threadIdx.x & 31;
    const int node = blockIdx.x * 8 + wid;
    if (node >= NN) return;

    int deg = g_cnt[node];
    if (deg > CAP) deg = CAP;
    const int*   bsrc  = g_bsrc  + (size_t)node * CAP;
    const float* bdist = g_bdist + (size_t)node * CAP;

    float xr[16];
    {
        const uint4* xrp = (const uint4*)(g_xrb + (size_t)node * HID + lane * 16);
        uint4 p0 = xrp[0], p1 = xrp[1];
        const __nv_bfloat162* h0 = (const __nv_bfloat162*)&p0;
        const __nv_bfloat162* h1 = (const __nv_bfloat162*)&p1;
#pragma unroll
        for (int q = 0; q < 4; q++) {
            float2 f0 = __bfloat1622float2(h0[q]);
            float2 f1 = __bfloat1622float2(h1[q]);
            xr[q * 2 + 0] = f0.x; xr[q * 2 + 1] = f0.y;
            xr[8 + q * 2 + 0] = f1.x; xr[8 + q * 2 + 1] = f1.y;
        }
    }
    float we[16], at[16];
#pragma unroll
    for (int q = 0; q < 4; q++) {
        float4 w = sWe[lane * 4 + q], t = sAtt[lane * 4 + q];
        we[q * 4 + 0] = w.x; we[q * 4 + 1] = w.y; we[q * 4 + 2] = w.z; we[q * 4 + 3] = w.w;
        at[q * 4 + 0] = t.x; at[q * 4 + 1] = t.y; at[q * 4 + 2] = t.z; at[q * 4 + 3] = t.w;
    }

    float denom = 0.f;
    float acc[16];
#pragma unroll
    for (int i = 0; i < 16; i++) acc[i] = 0.f;

    float dCur = bdist[0];
    uint4 p0c, p1c;
    {
        const uint4* xp = (const uint4*)(g_xlb + (size_t)bsrc[0] * HID + lane * 16);
        p0c = xp[0]; p1c = xp[1];
    }
    for (int j = 0; j < deg; j++) {
        uint4 p0 = p0c, p1 = p1c;
        const float dv = dCur;
        if (j + 1 < deg) {
            int sN = bsrc[j + 1];
            dCur = bdist[j + 1];
            const uint4* xp = (const uint4*)(g_xlb + (size_t)sN * HID + lane * 16);
            p0c = xp[0]; p1c = xp[1];
        }

        float a[16];
        {
            const __nv_bfloat162* h0 = (const __nv_bfloat162*)&p0;
            const __nv_bfloat162* h1 = (const __nv_bfloat162*)&p1;
#pragma unroll
            for (int q = 0; q < 4; q++) {
                float2 f0 = __bfloat1622float2(h0[q]);
                float2 f1 = __bfloat1622float2(h1[q]);
                a[q * 2 + 0] = f0.x; a[q * 2 + 1] = f0.y;
                a[8 + q * 2 + 0] = f1.x; a[8 + q * 2 + 1] = f1.y;
            }
        }

        float partial = 0.f;
#pragma unroll
        for (int i = 0; i < 16; i++) {
            float v = a[i] + xr[i] + dv * we[i];
            v = v > 0.f ? v : 0.2f * v;
            partial += v * at[i];
        }
        partial += __shfl_xor_sync(0xffffffffu, partial, 1);
        partial += __shfl_xor_sync(0xffffffffu, partial, 2);
        float ex = expf(partial);   // softmax shift-invariant; scores O(1)
        denom += ex;
#pragma unroll
        for (int i = 0; i < 16; i++) acc[i] += ex * a[i];
    }

    const float inv = 1.f / denom;      // self-loop => denom > 0

    const float* bp = bias + lane * 16;
    bf16* hbp = g_hb + (size_t)node * HID + lane * 16;
#pragma unroll
    for (int i = 0; i < 16; i += 2) {
        float v0 = acc[i] * inv + bp[i];
        float v1 = acc[i + 1] * inv + bp[i + 1];
        v0 = v0 > 0.f ? v0 : expm1f(v0);
        v1 = v1 > 0.f ? v1 : expm1f(v1);
        *(__nv_bfloat162*)(hbp + i) =
            __nv_bfloat162(__float2bfloat16(v0), __float2bfloat16(v1));
    }
}

// ---------------- final: logits = h @ Wa + ba; log_softmax (h = bf16 hb) ----
__global__ void final_kernel(const float* __restrict__ Wa,
                             const float* __restrict__ ba,
                             float* __restrict__ out)
{
    const int row = blockIdx.x * (blockDim.x >> 5) + (threadIdx.x >> 5);
    const int lane = threadIdx.x & 31;
    if (row >= NN) return;

    const bf16* hrow = g_hb + (size_t)row * HID;
    float acc[NCLS];
#pragma unroll
    for (int c = 0; c < NCLS; c++) acc[c] = 0.f;

    for (int k = lane * 2; k < HID; k += 64) {
        float2 hv = __bfloat1622float2(*(const __nv_bfloat162*)(hrow + k));
        const float* w0 = Wa + (size_t)k * NCLS;
        const float* w1 = w0 + NCLS;
#pragma unroll
        for (int c = 0; c < NCLS; c++) acc[c] += hv.x * w0[c] + hv.y * w1[c];
    }
#pragma unroll
    for (int off = 16; off > 0; off >>= 1)
#pragma unroll
        for (int c = 0; c < NCLS; c++)
            acc[c] += __shfl_xor_sync(0xffffffffu, acc[c], off);

    if (lane == 0) {
        float z[NCLS], mx = -1e30f;
#pragma unroll
        for (int c = 0; c < NCLS; c++) { z[c] = acc[c] + ba[c]; mx = fmaxf(mx, z[c]); }
        float s = 0.f;
#pragma unroll
        for (int c = 0; c < NCLS; c++) s += expf(z[c] - mx);
        float lse = mx + logf(s);
#pragma unroll
        for (int c = 0; c < NCLS; c++) out[(size_t)row * NCLS + c] = z[c] - lse;
    }
}

// ---------------- launch ----------------
extern "C" void kernel_launch(void* const* d_in, const int* in_sizes, int n_in,
                              void* d_out, int out_size)
{
    const float* x    = (const float*)d_in[0];
    const int*   ei   = (const int*)d_in[1];      // int32 (JAX x64 disabled)
    const float* dist = (const float*)d_in[2];
    const float* Wb   = (const float*)d_in[3];
    const float* bb   = (const float*)d_in[4];
    const float* Wl   = (const float*)d_in[5];
    const float* bl   = (const float*)d_in[6];
    const float* Wr   = (const float*)d_in[7];
    const float* br   = (const float*)d_in[8];
    const float* We   = (const float*)d_in[9];
    const float* att  = (const float*)d_in[10];
    const float* bc   = (const float*)d_in[11];
    const float* Wa   = (const float*)d_in[12];
    const float* ba   = (const float*)d_in[13];
    float* out = (float*)d_out;

    bf16 *phb, *pxb, *pxlb, *pxrb, *pwbT, *pwlT, *pwrT;
    cudaGetSymbolAddress((void**)&phb,  g_hb);
    cudaGetSymbolAddress((void**)&pxb,  g_xb);
    cudaGetSymbolAddress((void**)&pxlb, g_xlb);
    cudaGetSymbolAddress((void**)&pxrb, g_xrb);
    cudaGetSymbolAddress((void**)&pwbT, g_wbT);
    cudaGetSymbolAddress((void**)&pwlT, g_wlT);
    cudaGetSymbolAddress((void**)&pwrT, g_wrT);

    cudaFuncSetAttribute(bf16gemm, cudaFuncAttributeMaxDynamicSharedMemorySize, GEMM_SMEM);

    // ---- prep (fcnn GEMM at launch #4 for ncu capture) ----
    conv_x_zero<<<(NN * FIN + 255) / 256, 256>>>(x);                        // 1
    transp_bf16_batch7<<<dim3(HID / 32, HID / 32, 7), dim3(32, 8)>>>(Wl, Wr, Wb); // 2
    bucket_kernel<<<(ETOT + 255) / 256, 256>>>(ei, dist);                   // 3
    // fcnn_before: hb = bf16(elu(x @ Wb + bb))                              // 4
    bf16gemm<<<dim3(HID / TILE_N, (NN + 127) / 128), 256, GEMM_SMEM>>>(
        pxb, pwbT, nullptr, bb, nullptr, phb, nullptr, NN, FIN, 1);

    for (int i = 0; i < 3; i++) {
        // fused dual GEMM: xlb = hb @ Wl^T + bl ; xrb = hb @ Wr^T + br (bf16)
        bf16gemm<<<dim3(2 * HID / TILE_N, (NN + 127) / 128), 256, GEMM_SMEM>>>(
            phb, pwlT + (size_t)i * HID * HID, pwrT + (size_t)i * HID * HID,
            bl + i * HID, br + i * HID, pxlb, pxrb, NN, HID, 0);
        edge_fused<<<(NN + 7) / 8, 256>>>(We + (size_t)i * HID,
                                          att + (size_t)i * HID,
                                          bc + (size_t)i * HID);
    }

    final_kernel<<<(NN + 7) / 8, 256>>>(Wa, ba, out);
}

// round 14
// speedup vs baseline: 1.0397x; 1.0397x over previous
#include <cuda_runtime.h>
#include <cuda_bf16.h>
#include <math.h>
#include <stdint.h>

typedef __nv_bfloat16 bf16;

#define NN   10000
#define EE   160000
#define ETOT 170000   // EE + NN self loops
#define FIN  128
#define HID  512
#define HH   8
#define CC   64
#define NCLS 10
#define CAP  128      // per-node in-edge bucket capacity (P(overflow) ~ 1e-60)

// ---------------- scratch (device globals; no allocs allowed) ----------------
__device__ bf16  g_hb[NN * HID];          // bf16 h (GEMM A input + final input)
__device__ bf16  g_xb[NN * FIN];          // bf16 x
__device__ bf16  g_xlb[NN * HID];         // bf16 xl
__device__ bf16  g_xrb[NN * HID];         // bf16 xr
__device__ bf16  g_wbT[HID * FIN];        // Wb^T  [n][k]
__device__ bf16  g_wlT[3 * HID * HID];    // Wl^T per layer
__device__ bf16  g_wrT[3 * HID * HID];    // Wr^T per layer
__device__ int   g_cnt[NN];
__device__ int   g_bsrc[(size_t)NN * CAP];
__device__ float g_bdist[(size_t)NN * CAP];

// ---------------- fused: convert x to bf16 AND zero g_cnt -------------------
__global__ void conv_x_zero(const float* __restrict__ x)
{
    int i = blockIdx.x * blockDim.x + threadIdx.x;
    if (i < NN * FIN) g_xb[i] = __float2bfloat16(x[i]);
    if (i < NN) g_cnt[i] = 0;
}

// batched transpose+convert for all 7 weight matrices:
// z=0..2: Wl[z] (512x512), z=3..5: Wr[z-3], z=6: Wb (128x512, y<4 only)
__global__ void transp_bf16_batch7(const float* __restrict__ Wl,
                                   const float* __restrict__ Wr,
                                   const float* __restrict__ Wb)
{
    __shared__ float tile[32][33];
    int z = blockIdx.z;
    const float* src;
    bf16* dst;
    int K;
    if (z < 3)      { src = Wl + (size_t)z * HID * HID;       dst = g_wlT + (size_t)z * HID * HID;       K = HID; }
    else if (z < 6) { src = Wr + (size_t)(z - 3) * HID * HID; dst = g_wrT + (size_t)(z - 3) * HID * HID; K = HID; }
    else            { src = Wb;                               dst = g_wbT;                               K = FIN;
                      if (blockIdx.y >= FIN / 32) return; }
    int k0 = blockIdx.y * 32, n0 = blockIdx.x * 32;
    int tx = threadIdx.x, ty = threadIdx.y;   // 32 x 8
#pragma unroll
    for (int i = 0; i < 32; i += 8)
        tile[ty + i][tx] = src[(size_t)(k0 + ty + i) * HID + n0 + tx];
    __syncthreads();
#pragma unroll
    for (int i = 0; i < 32; i += 8)
        dst[(size_t)(n0 + ty + i) * K + k0 + tx] = __float2bfloat16(tile[tx][ty + i]);
}

// ---------------- bucket build ----------------------------------------------
__global__ void bucket_kernel(const int* __restrict__ ei,
                              const float* __restrict__ dist)
{
    int e = blockIdx.x * blockDim.x + threadIdx.x;
    if (e >= ETOT) return;
    int s, d; float dv;
    if (e < EE) { s = ei[e]; d = ei[EE + e]; dv = dist[e]; }
    else        { s = d = e - EE; dv = 0.f; }
    int pos = atomicAdd(&g_cnt[d], 1);
    if (pos < CAP) {
        g_bsrc [(size_t)d * CAP + pos] = s;
        g_bdist[(size_t)d * CAP + pos] = dv;
    }
}

// ---------------- bf16 tensor-core GEMM (R12-proven config) -----------------
// Cb[M,N] = bf16(A[M,K] @ B^T + bias [elu]), B stored [N][K] bf16.
// 128x128 tile, 256 thr, K-chunk 32, 4-stage cp.async ring (distance 3,
// issue moved BEFORE compute for deeper overlap), ldmatrix fragments.
__device__ __forceinline__ void mma_bf16(float* c, const uint32_t* a, const uint32_t* b)
{
    asm volatile(
        "mma.sync.aligned.m16n8k16.row.col.f32.bf16.bf16.f32 "
        "{%0,%1,%2,%3}, {%4,%5,%6,%7}, {%8,%9}, {%0,%1,%2,%3};"
        : "+f"(c[0]), "+f"(c[1]), "+f"(c[2]), "+f"(c[3])
        : "r"(a[0]), "r"(a[1]), "r"(a[2]), "r"(a[3]), "r"(b[0]), "r"(b[1]));
}
__device__ __forceinline__ void cp16(uint32_t dst, const void* src)
{
    asm volatile("cp.async.cg.shared.global [%0], [%1], 16;" :: "r"(dst), "l"(src));
}
__device__ __forceinline__ void ldsm4(uint32_t* r, uint32_t addr)
{
    asm volatile("ldmatrix.sync.aligned.m8n8.x4.shared.b16 {%0,%1,%2,%3}, [%4];"
                 : "=r"(r[0]), "=r"(r[1]), "=r"(r[2]), "=r"(r[3]) : "r"(addr));
}

#define STAGE_BYTES 20480                  // A: 128*80 + B: 128*80
#define GEMM_SMEM   (4 * STAGE_BYTES)      // 81920, dynamic (occ 2: 160KB/SM)

__global__ void __launch_bounds__(256, 2)
bf16gemm(const bf16* __restrict__ A,
         const bf16* __restrict__ B0, const bf16* __restrict__ B1,
         const float* __restrict__ bias0, const float* __restrict__ bias1,
         bf16* __restrict__ Cb0, bf16* __restrict__ Cb1,
         int M, int K, int doElu)
{
    extern __shared__ __align__(16) unsigned char smem[];
    const int N = HID;

    const int tid  = threadIdx.x;
    const int wid  = tid >> 5;
    const int lane = tid & 31;
    const int g    = lane >> 2;
    const int tg   = lane & 3;

    const bf16* B = B0;
    bf16* Cb = Cb0;
    const float* bi = bias0;
    int bx = blockIdx.x;
    if (B1 != nullptr && bx >= ((int)gridDim.x >> 1)) {
        B = B1; Cb = Cb1; bi = bias1; bx -= (int)gridDim.x >> 1;
    }
    const int m0 = blockIdx.y * 128;
    const int n0 = bx * 128;
    const int warpM = (wid >> 2) * 64;
    const int warpN = (wid & 3) * 32;

    const uint32_t sbase = (uint32_t)__cvta_generic_to_shared(smem);

    const int lrow = tid >> 2;          // cp.async row for i=0; i adds 64
    const int lq   = tid & 3;

    uint32_t aOff[4];
#pragma unroll
    for (int mt = 0; mt < 4; mt++)
        aOff[mt] = (uint32_t)((warpM + mt * 16 + (lane & 15)) * 80 + (lane >> 4) * 16);
    uint32_t bOff[2];
#pragma unroll
    for (int np = 0; np < 2; np++)
        bOff[np] = (uint32_t)(10240 +
                   (warpN + np * 16 + (lane & 7) + ((lane & 16) ? 8 : 0)) * 80 +
                   ((lane >> 3) & 1) * 16);

    float acc[4][4][4];
#pragma unroll
    for (int mt = 0; mt < 4; mt++)
#pragma unroll
        for (int nt = 0; nt < 4; nt++)
#pragma unroll
            for (int i = 0; i < 4; i++) acc[mt][nt][i] = 0.f;

    const int nStages = K >> 5;

    auto issue = [&](int buf, int ks) {
        uint32_t sA = sbase + buf * STAGE_BYTES;
        uint32_t sB = sA + 10240;
        int k0 = ks << 5;
#pragma unroll
        for (int i = 0; i < 2; i++) {
            int row = lrow + i * 64;
            int ar = m0 + row; if (ar >= M) ar = M - 1;
            cp16(sA + row * 80 + lq * 16, A + (size_t)ar * K + k0 + lq * 8);
            cp16(sB + row * 80 + lq * 16, B + (size_t)(n0 + row) * K + k0 + lq * 8);
        }
        asm volatile("cp.async.commit_group;");
    };

    issue(0, 0);
    if (nStages > 1) issue(1, 1);
    if (nStages > 2) issue(2, 2);

    for (int ks = 0; ks < nStages; ks++) {
        int rem = nStages - 1 - ks;
        if (rem >= 2)      asm volatile("cp.async.wait_group 2;");
        else if (rem == 1) asm volatile("cp.async.wait_group 1;");
        else               asm volatile("cp.async.wait_group 0;");
        __syncthreads();

        // prefetch EARLY: buffer (ks+3)&3 held stage ks-1, fully consumed
        // before this iteration's barrier -> safe, and the loads overlap
        // this stage's MMAs instead of starting after them.
        if (ks + 3 < nStages) issue((ks + 3) & 3, ks + 3);

        const uint32_t stage = sbase + (ks & 3) * STAGE_BYTES;

#pragma unroll
        for (int kk = 0; kk < 32; kk += 16) {
            const uint32_t kb = (kk >> 1) * 4;
            uint32_t a[4][4], b[2][4];
#pragma unroll
            for (int mt = 0; mt < 4; mt++)
                ldsm4(a[mt], stage + aOff[mt] + kb);
#pragma unroll
            for (int np = 0; np < 2; np++)
                ldsm4(b[np], stage + bOff[np] + kb);
#pragma unroll
            for (int mt = 0; mt < 4; mt++) {
                mma_bf16(acc[mt][0], a[mt], &b[0][0]);
                mma_bf16(acc[mt][1], a[mt], &b[0][2]);
                mma_bf16(acc[mt][2], a[mt], &b[1][0]);
                mma_bf16(acc[mt][3], a[mt], &b[1][2]);
            }
        }
    }

#pragma unroll
    for (int mt = 0; mt < 4; mt++) {
        int row0 = m0 + warpM + mt * 16 + g;
        int row1 = row0 + 8;
#pragma unroll
        for (int nt = 0; nt < 4; nt++) {
            int col = n0 + warpN + nt * 8 + tg * 2;
            float bx0 = bi[col], bx1 = bi[col + 1];
            float v0 = acc[mt][nt][0] + bx0;
            float v1 = acc[mt][nt][1] + bx1;
            float v2 = acc[mt][nt][2] + bx0;
            float v3 = acc[mt][nt][3] + bx1;
            if (doElu) {
                v0 = v0 > 0.f ? v0 : expm1f(v0);
                v1 = v1 > 0.f ? v1 : expm1f(v1);
                v2 = v2 > 0.f ? v2 : expm1f(v2);
                v3 = v3 > 0.f ? v3 : expm1f(v3);
            }
            if (row0 < M)
                *(__nv_bfloat162*)(Cb + (size_t)row0 * N + col) =
                    __nv_bfloat162(__float2bfloat16(v0), __float2bfloat16(v1));
            if (row1 < M)
                *(__nv_bfloat162*)(Cb + (size_t)row1 * N + col) =
                    __nv_bfloat162(__float2bfloat16(v2), __float2bfloat16(v3));
        }
    }
}

// ---------------- fused edge kernel: single pass, bf16, data-prefetch -------
__global__ void __launch_bounds__(256)
edge_fused(const float* __restrict__ We, const float* __restrict__ att,
           const float* __restrict__ bias)
{
    __shared__ float4 sWe[HID / 4];
    __shared__ float4 sAtt[HID / 4];

    for (int i = threadIdx.x; i < HID / 4; i += blockDim.x) {
        sWe[i]  = ((const float4*)We)[i];
        sAtt[i] = ((const float4*)att)[i];
    }
    __syncthreads();

    const int wid  = threadIdx.x >> 5;
    const int lane = threadIdx.x & 31;
    const int node = blockIdx.x * 8 + wid;
    if (node >= NN) return;

    int deg = g_cnt[node];
    if (deg > CAP) deg = CAP;
    const int*   bsrc  = g_bsrc  + (size_t)node * CAP;
    const float* bdist = g_bdist + (size_t)node * CAP;

    float xr[16];
    {
        const uint4* xrp = (const uint4*)(g_xrb + (size_t)node * HID + lane * 16);
        uint4 p0 = xrp[0], p1 = xrp[1];
        const __nv_bfloat162* h0 = (const __nv_bfloat162*)&p0;
        const __nv_bfloat162* h1 = (const __nv_bfloat162*)&p1;
#pragma unroll
        for (int q = 0; q < 4; q++) {
            float2 f0 = __bfloat1622float2(h0[q]);
            float2 f1 = __bfloat1622float2(h1[q]);
            xr[q * 2 + 0] = f0.x; xr[q * 2 + 1] = f0.y;
            xr[8 + q * 2 + 0] = f1.x; xr[8 + q * 2 + 1] = f1.y;
        }
    }
    float we[16], at[16];
#pragma unroll
    for (int q = 0; q < 4; q++) {
        float4 w = sWe[lane * 4 + q], t = sAtt[lane * 4 + q];
        we[q * 4 + 0] = w.x; we[q * 4 + 1] = w.y; we[q * 4 + 2] = w.z; we[q * 4 + 3] = w.w;
        at[q * 4 + 0] = t.x; at[q * 4 + 1] = t.y; at[q * 4 + 2] = t.z; at[q * 4 + 3] = t.w;
    }

    float denom = 0.f;
    float acc[16];
#pragma unroll
    for (int i = 0; i < 16; i++) acc[i] = 0.f;

    float dCur = bdist[0];
    uint4 p0c, p1c;
    {
        const uint4* xp = (const uint4*)(g_xlb + (size_t)bsrc[0] * HID + lane * 16);
        p0c = xp[0]; p1c = xp[1];
    }
    for (int j = 0; j < deg; j++) {
        uint4 p0 = p0c, p1 = p1c;
        const float dv = dCur;
        if (j + 1 < deg) {
            int sN = bsrc[j + 1];
            dCur = bdist[j + 1];
            const uint4* xp = (const uint4*)(g_xlb + (size_t)sN * HID + lane * 16);
            p0c = xp[0]; p1c = xp[1];
        }

        float a[16];
        {
            const __nv_bfloat162* h0 = (const __nv_bfloat162*)&p0;
            const __nv_bfloat162* h1 = (const __nv_bfloat162*)&p1;
#pragma unroll
            for (int q = 0; q < 4; q++) {
                float2 f0 = __bfloat1622float2(h0[q]);
                float2 f1 = __bfloat1622float2(h1[q]);
                a[q * 2 + 0] = f0.x; a[q * 2 + 1] = f0.y;
                a[8 + q * 2 + 0] = f1.x; a[8 + q * 2 + 1] = f1.y;
            }
        }

        float partial = 0.f;
#pragma unroll
        for (int i = 0; i < 16; i++) {
            float v = a[i] + xr[i] + dv * we[i];
            v = v > 0.f ? v : 0.2f * v;
            partial += v * at[i];
        }
        partial += __shfl_xor_sync(0xffffffffu, partial, 1);
        partial += __shfl_xor_sync(0xffffffffu, partial, 2);
        float ex = expf(partial);   // softmax shift-invariant; scores O(1)
        denom += ex;
#pragma unroll
        for (int i = 0; i < 16; i++) acc[i] += ex * a[i];
    }

    const float inv = 1.f / denom;      // self-loop => denom > 0

    const float* bp = bias + lane * 16;
    bf16* hbp = g_hb + (size_t)node * HID + lane * 16;
#pragma unroll
    for (int i = 0; i < 16; i += 2) {
        float v0 = acc[i] * inv + bp[i];
        float v1 = acc[i + 1] * inv + bp[i + 1];
        v0 = v0 > 0.f ? v0 : expm1f(v0);
        v1 = v1 > 0.f ? v1 : expm1f(v1);
        *(__nv_bfloat162*)(hbp + i) =
            __nv_bfloat162(__float2bfloat16(v0), __float2bfloat16(v1));
    }
}

// ---------------- final: logits = h @ Wa + ba; log_softmax (h = bf16 hb) ----
__global__ void final_kernel(const float* __restrict__ Wa,
                             const float* __restrict__ ba,
                             float* __restrict__ out)
{
    const int row = blockIdx.x * (blockDim.x >> 5) + (threadIdx.x >> 5);
    const int lane = threadIdx.x & 31;
    if (row >= NN) return;

    const bf16* hrow = g_hb + (size_t)row * HID;
    float acc[NCLS];
#pragma unroll
    for (int c = 0; c < NCLS; c++) acc[c] = 0.f;

    for (int k = lane * 2; k < HID; k += 64) {
        float2 hv = __bfloat1622float2(*(const __nv_bfloat162*)(hrow + k));
        const float* w0 = Wa + (size_t)k * NCLS;
        const float* w1 = w0 + NCLS;
#pragma unroll
        for (int c = 0; c < NCLS; c++) acc[c] += hv.x * w0[c] + hv.y * w1[c];
    }
#pragma unroll
    for (int off = 16; off > 0; off >>= 1)
#pragma unroll
        for (int c = 0; c < NCLS; c++)
            acc[c] += __shfl_xor_sync(0xffffffffu, acc[c], off);

    if (lane == 0) {
        float z[NCLS], mx = -1e30f;
#pragma unroll
        for (int c = 0; c < NCLS; c++) { z[c] = acc[c] + ba[c]; mx = fmaxf(mx, z[c]); }
        float s = 0.f;
#pragma unroll
        for (int c = 0; c < NCLS; c++) s += expf(z[c] - mx);
        float lse = mx + logf(s);
#pragma unroll
        for (int c = 0; c < NCLS; c++) out[(size_t)row * NCLS + c] = z[c] - lse;
    }
}

// ---------------- launch ----------------
extern "C" void kernel_launch(void* const* d_in, const int* in_sizes, int n_in,
                              void* d_out, int out_size)
{
    const float* x    = (const float*)d_in[0];
    const int*   ei   = (const int*)d_in[1];      // int32 (JAX x64 disabled)
    const float* dist = (const float*)d_in[2];
    const float* Wb   = (const float*)d_in[3];
    const float* bb   = (const float*)d_in[4];
    const float* Wl   = (const float*)d_in[5];
    const float* bl   = (const float*)d_in[6];
    const float* Wr   = (const float*)d_in[7];
    const float* br   = (const float*)d_in[8];
    const float* We   = (const float*)d_in[9];
    const float* att  = (const float*)d_in[10];
    const float* bc   = (const float*)d_in[11];
    const float* Wa   = (const float*)d_in[12];
    const float* ba   = (const float*)d_in[13];
    float* out = (float*)d_out;

    bf16 *phb, *pxb, *pxlb, *pxrb, *pwbT, *pwlT, *pwrT;
    cudaGetSymbolAddress((void**)&phb,  g_hb);
    cudaGetSymbolAddress((void**)&pxb,  g_xb);
    cudaGetSymbolAddress((void**)&pxlb, g_xlb);
    cudaGetSymbolAddress((void**)&pxrb, g_xrb);
    cudaGetSymbolAddress((void**)&pwbT, g_wbT);
    cudaGetSymbolAddress((void**)&pwlT, g_wlT);
    cudaGetSymbolAddress((void**)&pwrT, g_wrT);

    cudaFuncSetAttribute(bf16gemm, cudaFuncAttributeMaxDynamicSharedMemorySize, GEMM_SMEM);

    // ---- prep (fcnn GEMM at launch #4 for ncu capture) ----
    conv_x_zero<<<(NN * FIN + 255) / 256, 256>>>(x);                        // 1
    transp_bf16_batch7<<<dim3(HID / 32, HID / 32, 7), dim3(32, 8)>>>(Wl, Wr, Wb); // 2
    bucket_kernel<<<(ETOT + 255) / 256, 256>>>(ei, dist);                   // 3
    // fcnn_before: hb = bf16(elu(x @ Wb + bb))                              // 4
    bf16gemm<<<dim3(HID / 128, (NN + 127) / 128), 256, GEMM_SMEM>>>(
        pxb, pwbT, nullptr, bb, nullptr, phb, nullptr, NN, FIN, 1);

    for (int i = 0; i < 3; i++) {
        // fused dual GEMM: xlb = hb @ Wl^T + bl ; xrb = hb @ Wr^T + br (bf16)
        bf16gemm<<<dim3(2 * HID / 128, (NN + 127) / 128), 256, GEMM_SMEM>>>(
            phb, pwlT + (size_t)i * HID * HID, pwrT + (size_t)i * HID * HID,
            bl + i * HID, br + i * HID, pxlb, pxrb, NN, HID, 0);
        edge_fused<<<(NN + 7) / 8, 256>>>(We + (size_t)i * HID,
                                          att + (size_t)i * HID,
                                          bc + (size_t)i * HID);
    }

    final_kernel<<<(NN + 7) / 8, 256>>>(Wa, ba, out);
}

// round 16
// speedup vs baseline: 1.0990x; 1.0570x over previous
#include <cuda_runtime.h>
#include <cuda_bf16.h>
#include <math.h>
#include <stdint.h>

typedef __nv_bfloat16 bf16;

#define NN   10000
#define EE   160000
#define ETOT 170000   // EE + NN self loops
#define FIN  128
#define HID  512
#define HH   8
#define CC   64
#define NCLS 10
#define CAP  128      // per-node in-edge bucket capacity (P(overflow) ~ 1e-60)

// ---------------- scratch (device globals; no allocs allowed) ----------------
__device__ bf16  g_hb[NN * HID];          // bf16 h (GEMM A input + final input)
__device__ bf16  g_xb[NN * FIN];          // bf16 x
__device__ bf16  g_xlb[NN * HID];         // bf16 xl
__device__ bf16  g_xrb[NN * HID];         // bf16 xr
__device__ bf16  g_wbT[HID * FIN];        // Wb^T  [n][k]
__device__ bf16  g_wlT[3 * HID * HID];    // Wl^T per layer
__device__ bf16  g_wrT[3 * HID * HID];    // Wr^T per layer
__device__ int   g_cnt[NN];
__device__ int2  g_bpack[(size_t)NN * CAP];   // {src, dist bits}

// ---------------- fused: convert x to bf16 AND zero g_cnt -------------------
__global__ void conv_x_zero(const float* __restrict__ x)
{
    int i = blockIdx.x * blockDim.x + threadIdx.x;
    if (i < NN * FIN) g_xb[i] = __float2bfloat16(x[i]);
    if (i < NN) g_cnt[i] = 0;
}

// batched transpose+convert for all 7 weight matrices:
// z=0..2: Wl[z] (512x512), z=3..5: Wr[z-3], z=6: Wb (128x512, y<4 only)
__global__ void transp_bf16_batch7(const float* __restrict__ Wl,
                                   const float* __restrict__ Wr,
                                   const float* __restrict__ Wb)
{
    __shared__ float tile[32][33];
    int z = blockIdx.z;
    const float* src;
    bf16* dst;
    int K;
    if (z < 3)      { src = Wl + (size_t)z * HID * HID;       dst = g_wlT + (size_t)z * HID * HID;       K = HID; }
    else if (z < 6) { src = Wr + (size_t)(z - 3) * HID * HID; dst = g_wrT + (size_t)(z - 3) * HID * HID; K = HID; }
    else            { src = Wb;                               dst = g_wbT;                               K = FIN;
                      if (blockIdx.y >= FIN / 32) return; }
    int k0 = blockIdx.y * 32, n0 = blockIdx.x * 32;
    int tx = threadIdx.x, ty = threadIdx.y;   // 32 x 8
#pragma unroll
    for (int i = 0; i < 32; i += 8)
        tile[ty + i][tx] = src[(size_t)(k0 + ty + i) * HID + n0 + tx];
    __syncthreads();
#pragma unroll
    for (int i = 0; i < 32; i += 8)
        dst[(size_t)(n0 + ty + i) * K + k0 + tx] = __float2bfloat16(tile[tx][ty + i]);
}

// ---------------- bucket build (packed src+dist) ----------------------------
__global__ void bucket_kernel(const int* __restrict__ ei,
                              const float* __restrict__ dist)
{
    int e = blockIdx.x * blockDim.x + threadIdx.x;
    if (e >= ETOT) return;
    int s, d; float dv;
    if (e < EE) { s = ei[e]; d = ei[EE + e]; dv = dist[e]; }
    else        { s = d = e - EE; dv = 0.f; }
    int pos = atomicAdd(&g_cnt[d], 1);
    if (pos < CAP)
        g_bpack[(size_t)d * CAP + pos] = make_int2(s, __float_as_int(dv));
}

// ---------------- bf16 tensor-core GEMM (R12 structure, 5-stage ring) -------
// Cb[M,N] = bf16(A[M,K] @ B^T + bias [elu]), B stored [N][K] bf16.
// 128x128 tile, 256 thr, K-chunk 32, 5-stage cp.async ring (issue after
// compute, distance 4), ldmatrix fragments.
__device__ __forceinline__ void mma_bf16(float* c, const uint32_t* a, const uint32_t* b)
{
    asm volatile(
        "mma.sync.aligned.m16n8k16.row.col.f32.bf16.bf16.f32 "
        "{%0,%1,%2,%3}, {%4,%5,%6,%7}, {%8,%9}, {%0,%1,%2,%3};"
        : "+f"(c[0]), "+f"(c[1]), "+f"(c[2]), "+f"(c[3])
        : "r"(a[0]), "r"(a[1]), "r"(a[2]), "r"(a[3]), "r"(b[0]), "r"(b[1]));
}
__device__ __forceinline__ void cp16(uint32_t dst, const void* src)
{
    asm volatile("cp.async.cg.shared.global [%0], [%1], 16;" :: "r"(dst), "l"(src));
}
__device__ __forceinline__ void ldsm4(uint32_t* r, uint32_t addr)
{
    asm volatile("ldmatrix.sync.aligned.m8n8.x4.shared.b16 {%0,%1,%2,%3}, [%4];"
                 : "=r"(r[0]), "=r"(r[1]), "=r"(r[2]), "=r"(r[3]) : "r"(addr));
}

#define STAGE_BYTES 20480                  // A: 128*80 + B: 128*80
#define NSTAGE      5
#define GEMM_SMEM   (NSTAGE * STAGE_BYTES) // 102400; occ 2 = 200KB/SM

__global__ void __launch_bounds__(256, 2)
bf16gemm(const bf16* __restrict__ A,
         const bf16* __restrict__ B0, const bf16* __restrict__ B1,
         const float* __restrict__ bias0, const float* __restrict__ bias1,
         bf16* __restrict__ Cb0, bf16* __restrict__ Cb1,
         int M, int K, int doElu)
{
    extern __shared__ __align__(16) unsigned char smem[];
    const int N = HID;

    const int tid  = threadIdx.x;
    const int wid  = tid >> 5;
    const int lane = tid & 31;
    const int g    = lane >> 2;
    const int tg   = lane & 3;

    const bf16* B = B0;
    bf16* Cb = Cb0;
    const float* bi = bias0;
    int bx = blockIdx.x;
    if (B1 != nullptr && bx >= ((int)gridDim.x >> 1)) {
        B = B1; Cb = Cb1; bi = bias1; bx -= (int)gridDim.x >> 1;
    }
    const int m0 = blockIdx.y * 128;
    const int n0 = bx * 128;
    const int warpM = (wid >> 2) * 64;
    const int warpN = (wid & 3) * 32;

    const uint32_t sbase = (uint32_t)__cvta_generic_to_shared(smem);

    const int lrow = tid >> 2;          // cp.async row for i=0; i adds 64
    const int lq   = tid & 3;

    uint32_t aOff[4];
#pragma unroll
    for (int mt = 0; mt < 4; mt++)
        aOff[mt] = (uint32_t)((warpM + mt * 16 + (lane & 15)) * 80 + (lane >> 4) * 16);
    uint32_t bOff[2];
#pragma unroll
    for (int np = 0; np < 2; np++)
        bOff[np] = (uint32_t)(10240 +
                   (warpN + np * 16 + (lane & 7) + ((lane & 16) ? 8 : 0)) * 80 +
                   ((lane >> 3) & 1) * 16);

    float acc[4][4][4];
#pragma unroll
    for (int mt = 0; mt < 4; mt++)
#pragma unroll
        for (int nt = 0; nt < 4; nt++)
#pragma unroll
            for (int i = 0; i < 4; i++) acc[mt][nt][i] = 0.f;

    const int nStages = K >> 5;

    auto issue = [&](int buf, int ks) {
        uint32_t sA = sbase + buf * STAGE_BYTES;
        uint32_t sB = sA + 10240;
        int k0 = ks << 5;
#pragma unroll
        for (int i = 0; i < 2; i++) {
            int row = lrow + i * 64;
            int ar = m0 + row; if (ar >= M) ar = M - 1;
            cp16(sA + row * 80 + lq * 16, A + (size_t)ar * K + k0 + lq * 8);
            cp16(sB + row * 80 + lq * 16, B + (size_t)(n0 + row) * K + k0 + lq * 8);
        }
        asm volatile("cp.async.commit_group;");
    };

    issue(0, 0);
    if (nStages > 1) issue(1, 1);
    if (nStages > 2) issue(2, 2);
    if (nStages > 3) issue(3, 3);

    for (int ks = 0; ks < nStages; ks++) {
        int rem = nStages - 1 - ks;
        if (rem >= 3)      asm volatile("cp.async.wait_group 3;");
        else if (rem == 2) asm volatile("cp.async.wait_group 2;");
        else if (rem == 1) asm volatile("cp.async.wait_group 1;");
        else               asm volatile("cp.async.wait_group 0;");
        __syncthreads();

        const uint32_t stage = sbase + (ks % NSTAGE) * STAGE_BYTES;

#pragma unroll
        for (int kk = 0; kk < 32; kk += 16) {
            const uint32_t kb = (kk >> 1) * 4;
            uint32_t a[4][4], b[2][4];
#pragma unroll
            for (int mt = 0; mt < 4; mt++)
                ldsm4(a[mt], stage + aOff[mt] + kb);
#pragma unroll
            for (int np = 0; np < 2; np++)
                ldsm4(b[np], stage + bOff[np] + kb);
#pragma unroll
            for (int mt = 0; mt < 4; mt++) {
                mma_bf16(acc[mt][0], a[mt], &b[0][0]);
                mma_bf16(acc[mt][1], a[mt], &b[0][2]);
                mma_bf16(acc[mt][2], a[mt], &b[1][0]);
                mma_bf16(acc[mt][3], a[mt], &b[1][2]);
            }
        }

        // issue after compute (R12-proven): buffer (ks+4)%5 held stage ks-1,
        // consumed in iteration ks-1 -> safe.
        if (ks + 4 < nStages) issue((ks + 4) % NSTAGE, ks + 4);
    }

#pragma unroll
    for (int mt = 0; mt < 4; mt++) {
        int row0 = m0 + warpM + mt * 16 + g;
        int row1 = row0 + 8;
#pragma unroll
        for (int nt = 0; nt < 4; nt++) {
            int col = n0 + warpN + nt * 8 + tg * 2;
            float bx0 = bi[col], bx1 = bi[col + 1];
            float v0 = acc[mt][nt][0] + bx0;
            float v1 = acc[mt][nt][1] + bx1;
            float v2 = acc[mt][nt][2] + bx0;
            float v3 = acc[mt][nt][3] + bx1;
            if (doElu) {
                v0 = v0 > 0.f ? v0 : expm1f(v0);
                v1 = v1 > 0.f ? v1 : expm1f(v1);
                v2 = v2 > 0.f ? v2 : expm1f(v2);
                v3 = v3 > 0.f ? v3 : expm1f(v3);
            }
            if (row0 < M)
                *(__nv_bfloat162*)(Cb + (size_t)row0 * N + col) =
                    __nv_bfloat162(__float2bfloat16(v0), __float2bfloat16(v1));
            if (row1 < M)
                *(__nv_bfloat162*)(Cb + (size_t)row1 * N + col) =
                    __nv_bfloat162(__float2bfloat16(v2), __float2bfloat16(v3));
        }
    }
}

// ---------------- fused edge kernel: single pass, bf16, data-prefetch -------
__global__ void __launch_bounds__(256)
edge_fused(const float* __restrict__ We, const float* __restrict__ att,
           const float* __restrict__ bias)
{
    __shared__ float4 sWe[HID / 4];
    __shared__ float4 sAtt[HID / 4];

    for (int i = threadIdx.x; i < HID / 4; i += blockDim.x) {
        sWe[i]  = ((const float4*)We)[i];
        sAtt[i] = ((const float4*)att)[i];
    }
    __syncthreads();

    const int wid  = threadIdx.x >> 5;
    const int lane = threadIdx.x & 31;
    const int node = blockIdx.x * 8 + wid;
    if (node >= NN) return;

    int deg = g_cnt[node];
    if (deg > CAP) deg = CAP;
    const int2* bp2 = g_bpack + (size_t)node * CAP;

    float xr[16];
    {
        const uint4* xrp = (const uint4*)(g_xrb + (size_t)node * HID + lane * 16);
        uint4 p0 = xrp[0], p1 = xrp[1];
        const __nv_bfloat162* h0 = (const __nv_bfloat162*)&p0;
        const __nv_bfloat162* h1 = (const __nv_bfloat162*)&p1;
#pragma unroll
        for (int q = 0; q < 4; q++) {
            float2 f0 = __bfloat1622float2(h0[q]);
            float2 f1 = __bfloat1622float2(h1[q]);
            xr[q * 2 + 0] = f0.x; xr[q * 2 + 1] = f0.y;
            xr[8 + q * 2 + 0] = f1.x; xr[8 + q * 2 + 1] = f1.y;
        }
    }
    float we[16], at[16];
#pragma unroll
    for (int q = 0; q < 4; q++) {
        float4 w = sWe[lane * 4 + q], t = sAtt[lane * 4 + q];
        we[q * 4 + 0] = w.x; we[q * 4 + 1] = w.y; we[q * 4 + 2] = w.z; we[q * 4 + 3] = w.w;
        at[q * 4 + 0] = t.x; at[q * 4 + 1] = t.y; at[q * 4 + 2] = t.z; at[q * 4 + 3] = t.w;
    }

    float denom = 0.f;
    float acc[16];
#pragma unroll
    for (int i = 0; i < 16; i++) acc[i] = 0.f;

    int2 eCur = bp2[0];
    uint4 p0c, p1c;
    {
        const uint4* xp = (const uint4*)(g_xlb + (size_t)eCur.x * HID + lane * 16);
        p0c = xp[0]; p1c = xp[1];
    }
    for (int j = 0; j < deg; j++) {
        uint4 p0 = p0c, p1 = p1c;
        const float dv = __int_as_float(eCur.y);
        if (j + 1 < deg) {
            eCur = bp2[j + 1];
            const uint4* xp = (const uint4*)(g_xlb + (size_t)eCur.x * HID + lane * 16);
            p0c = xp[0]; p1c = xp[1];
        }

        float a[16];
        {
            const __nv_bfloat162* h0 = (const __nv_bfloat162*)&p0;
            const __nv_bfloat162* h1 = (const __nv_bfloat162*)&p1;
#pragma unroll
            for (int q = 0; q < 4; q++) {
                float2 f0 = __bfloat1622float2(h0[q]);
                float2 f1 = __bfloat1622float2(h1[q]);
                a[q * 2 + 0] = f0.x; a[q * 2 + 1] = f0.y;
                a[8 + q * 2 + 0] = f1.x; a[8 + q * 2 + 1] = f1.y;
            }
        }

        float partial = 0.f;
#pragma unroll
        for (int i = 0; i < 16; i++) {
            float v = a[i] + xr[i] + dv * we[i];
            v = v > 0.f ? v : 0.2f * v;
            partial += v * at[i];
        }
        partial += __shfl_xor_sync(0xffffffffu, partial, 1);
        partial += __shfl_xor_sync(0xffffffffu, partial, 2);
        float ex = __expf(partial);   // softmax shift-invariant; scores O(1)
        denom += ex;
#pragma unroll
        for (int i = 0; i < 16; i++) acc[i] += ex * a[i];
    }

    const float inv = 1.f / denom;      // self-loop => denom > 0

    const float* bp = bias + lane * 16;
    bf16* hbp = g_hb + (size_t)node * HID + lane * 16;
#pragma unroll
    for (int i = 0; i < 16; i += 2) {
        float v0 = acc[i] * inv + bp[i];
        float v1 = acc[i + 1] * inv + bp[i + 1];
        v0 = v0 > 0.f ? v0 : expm1f(v0);
        v1 = v1 > 0.f ? v1 : expm1f(v1);
        *(__nv_bfloat162*)(hbp + i) =
            __nv_bfloat162(__float2bfloat16(v0), __float2bfloat16(v1));
    }
}

// ---------------- final: logits = h @ Wa + ba; log_softmax (h = bf16 hb) ----
__global__ void final_kernel(const float* __restrict__ Wa,
                             const float* __restrict__ ba,
                             float* __restrict__ out)
{
    const int row = blockIdx.x * (blockDim.x >> 5) + (threadIdx.x >> 5);
    const int lane = threadIdx.x & 31;
    if (row >= NN) return;

    const bf16* hrow = g_hb + (size_t)row * HID;
    float acc[NCLS];
#pragma unroll
    for (int c = 0; c < NCLS; c++) acc[c] = 0.f;

    for (int k = lane * 2; k < HID; k += 64) {
        float2 hv = __bfloat1622float2(*(const __nv_bfloat162*)(hrow + k));
        const float* w0 = Wa + (size_t)k * NCLS;
        const float* w1 = w0 + NCLS;
#pragma unroll
        for (int c = 0; c < NCLS; c++) acc[c] += hv.x * w0[c] + hv.y * w1[c];
    }
#pragma unroll
    for (int off = 16; off > 0; off >>= 1)
#pragma unroll
        for (int c = 0; c < NCLS; c++)
            acc[c] += __shfl_xor_sync(0xffffffffu, acc[c], off);

    if (lane == 0) {
        float z[NCLS], mx = -1e30f;
#pragma unroll
        for (int c = 0; c < NCLS; c++) { z[c] = acc[c] + ba[c]; mx = fmaxf(mx, z[c]); }
        float s = 0.f;
#pragma unroll
        for (int c = 0; c < NCLS; c++) s += expf(z[c] - mx);
        float lse = mx + logf(s);
#pragma unroll
        for (int c = 0; c < NCLS; c++) out[(size_t)row * NCLS + c] = z[c] - lse;
    }
}

// ---------------- launch ----------------
extern "C" void kernel_launch(void* const* d_in, const int* in_sizes, int n_in,
                              void* d_out, int out_size)
{
    const float* x    = (const float*)d_in[0];
    const int*   ei   = (const int*)d_in[1];      // int32 (JAX x64 disabled)
    const float* dist = (const float*)d_in[2];
    const float* Wb   = (const float*)d_in[3];
    const float* bb   = (const float*)d_in[4];
    const float* Wl   = (const float*)d_in[5];
    const float* bl   = (const float*)d_in[6];
    const float* Wr   = (const float*)d_in[7];
    const float* br   = (const float*)d_in[8];
    const float* We   = (const float*)d_in[9];
    const float* att  = (const float*)d_in[10];
    const float* bc   = (const float*)d_in[11];
    const float* Wa   = (const float*)d_in[12];
    const float* ba   = (const float*)d_in[13];
    float* out = (float*)d_out;

    bf16 *phb, *pxb, *pxlb, *pxrb, *pwbT, *pwlT, *pwrT;
    cudaGetSymbolAddress((void**)&phb,  g_hb);
    cudaGetSymbolAddress((void**)&pxb,  g_xb);
    cudaGetSymbolAddress((void**)&pxlb, g_xlb);
    cudaGetSymbolAddress((void**)&pxrb, g_xrb);
    cudaGetSymbolAddress((void**)&pwbT, g_wbT);
    cudaGetSymbolAddress((void**)&pwlT, g_wlT);
    cudaGetSymbolAddress((void**)&pwrT, g_wrT);

    cudaFuncSetAttribute(bf16gemm, cudaFuncAttributeMaxDynamicSharedMemorySize, GEMM_SMEM);

    // ---- prep; launch order puts the layer-0 DUAL GEMM at slot 4 (ncu) ----
    conv_x_zero<<<(NN * FIN + 255) / 256, 256>>>(x);                        // 1
    transp_bf16_batch7<<<dim3(HID / 32, HID / 32, 7), dim3(32, 8)>>>(Wl, Wr, Wb); // 2
    // fcnn_before: hb = bf16(elu(x @ Wb + bb))                              // 3
    bf16gemm<<<dim3(HID / 128, (NN + 127) / 128), 256, GEMM_SMEM>>>(
        pxb, pwbT, nullptr, bb, nullptr, phb, nullptr, NN, FIN, 1);

    for (int i = 0; i < 3; i++) {
        // fused dual GEMM: xlb = hb @ Wl^T + bl ; xrb = hb @ Wr^T + br      // 4 (i=0)
        bf16gemm<<<dim3(2 * HID / 128, (NN + 127) / 128), 256, GEMM_SMEM>>>(
            phb, pwlT + (size_t)i * HID * HID, pwrT + (size_t)i * HID * HID,
            bl + i * HID, br + i * HID, pxlb, pxrb, NN, HID, 0);
        if (i == 0)
            bucket_kernel<<<(ETOT + 255) / 256, 256>>>(ei, dist);           // 5
        edge_fused<<<(NN + 7) / 8, 256>>>(We + (size_t)i * HID,
                                          att + (size_t)i * HID,
                                          bc + (size_t)i * HID);
    }

    final_kernel<<<(NN + 7) / 8, 256>>>(Wa, ba, out);
}

// round 17
// speedup vs baseline: 1.1743x; 1.0685x over previous
#include <cuda_runtime.h>
#include <cuda_bf16.h>
#include <math.h>
#include <stdint.h>

typedef __nv_bfloat16 bf16;

#define NN   10000
#define EE   160000
#define ETOT 170000   // EE + NN self loops
#define FIN  128
#define HID  512
#define HH   8
#define CC   64
#define NCLS 10
#define CAP  128      // per-node in-edge bucket capacity (P(overflow) ~ 1e-60)

// ---------------- scratch (device globals; no allocs allowed) ----------------
__device__ bf16  g_hb[NN * HID];          // bf16 h (GEMM A input + final input)
__device__ bf16  g_xb[NN * FIN];          // bf16 x
__device__ bf16  g_xlb[NN * HID];         // bf16 xl
__device__ bf16  g_xrb[NN * HID];         // bf16 xr
__device__ bf16  g_wbT[HID * FIN];        // Wb^T  [n][k]
__device__ bf16  g_wlT[3 * HID * HID];    // Wl^T per layer
__device__ bf16  g_wrT[3 * HID * HID];    // Wr^T per layer
__device__ int   g_cnt[NN];
__device__ int2  g_bpack[(size_t)NN * CAP];   // {src, dist bits}

// ---------------- fused: convert x to bf16 AND zero g_cnt -------------------
__global__ void conv_x_zero(const float* __restrict__ x)
{
    int i = blockIdx.x * blockDim.x + threadIdx.x;
    if (i < NN * FIN) g_xb[i] = __float2bfloat16(x[i]);
    if (i < NN) g_cnt[i] = 0;
}

// batched transpose+convert for all 7 weight matrices:
// z=0..2: Wl[z] (512x512), z=3..5: Wr[z-3], z=6: Wb (128x512, y<4 only)
__global__ void transp_bf16_batch7(const float* __restrict__ Wl,
                                   const float* __restrict__ Wr,
                                   const float* __restrict__ Wb)
{
    __shared__ float tile[32][33];
    int z = blockIdx.z;
    const float* src;
    bf16* dst;
    int K;
    if (z < 3)      { src = Wl + (size_t)z * HID * HID;       dst = g_wlT + (size_t)z * HID * HID;       K = HID; }
    else if (z < 6) { src = Wr + (size_t)(z - 3) * HID * HID; dst = g_wrT + (size_t)(z - 3) * HID * HID; K = HID; }
    else            { src = Wb;                               dst = g_wbT;                               K = FIN;
                      if (blockIdx.y >= FIN / 32) return; }
    int k0 = blockIdx.y * 32, n0 = blockIdx.x * 32;
    int tx = threadIdx.x, ty = threadIdx.y;   // 32 x 8
#pragma unroll
    for (int i = 0; i < 32; i += 8)
        tile[ty + i][tx] = src[(size_t)(k0 + ty + i) * HID + n0 + tx];
    __syncthreads();
#pragma unroll
    for (int i = 0; i < 32; i += 8)
        dst[(size_t)(n0 + ty + i) * K + k0 + tx] = __float2bfloat16(tile[tx][ty + i]);
}

// ---------------- bucket build (packed src+dist) ----------------------------
__global__ void bucket_kernel(const int* __restrict__ ei,
                              const float* __restrict__ dist)
{
    int e = blockIdx.x * blockDim.x + threadIdx.x;
    if (e >= ETOT) return;
    int s, d; float dv;
    if (e < EE) { s = ei[e]; d = ei[EE + e]; dv = dist[e]; }
    else        { s = d = e - EE; dv = 0.f; }
    int pos = atomicAdd(&g_cnt[d], 1);
    if (pos < CAP)
        g_bpack[(size_t)d * CAP + pos] = make_int2(s, __float_as_int(dv));
}

// ---------------- bf16 tensor-core GEMM (champion config, frozen) -----------
// Cb[M,N] = bf16(A[M,K] @ B^T + bias [elu]), B stored [N][K] bf16.
// 128x128 tile, 256 thr, K-chunk 32, 5-stage cp.async ring (issue after
// compute, distance 4), ldmatrix fragments.
__device__ __forceinline__ void mma_bf16(float* c, const uint32_t* a, const uint32_t* b)
{
    asm volatile(
        "mma.sync.aligned.m16n8k16.row.col.f32.bf16.bf16.f32 "
        "{%0,%1,%2,%3}, {%4,%5,%6,%7}, {%8,%9}, {%0,%1,%2,%3};"
        : "+f"(c[0]), "+f"(c[1]), "+f"(c[2]), "+f"(c[3])
        : "r"(a[0]), "r"(a[1]), "r"(a[2]), "r"(a[3]), "r"(b[0]), "r"(b[1]));
}
__device__ __forceinline__ void cp16(uint32_t dst, const void* src)
{
    asm volatile("cp.async.cg.shared.global [%0], [%1], 16;" :: "r"(dst), "l"(src));
}
__device__ __forceinline__ void ldsm4(uint32_t* r, uint32_t addr)
{
    asm volatile("ldmatrix.sync.aligned.m8n8.x4.shared.b16 {%0,%1,%2,%3}, [%4];"
                 : "=r"(r[0]), "=r"(r[1]), "=r"(r[2]), "=r"(r[3]) : "r"(addr));
}

#define STAGE_BYTES 20480                  // A: 128*80 + B: 128*80
#define NSTAGE      5
#define GEMM_SMEM   (NSTAGE * STAGE_BYTES) // 102400; occ 2 = 200KB/SM

__global__ void __launch_bounds__(256, 2)
bf16gemm(const bf16* __restrict__ A,
         const bf16* __restrict__ B0, const bf16* __restrict__ B1,
         const float* __restrict__ bias0, const float* __restrict__ bias1,
         bf16* __restrict__ Cb0, bf16* __restrict__ Cb1,
         int M, int K, int doElu)
{
    extern __shared__ __align__(16) unsigned char smem[];
    const int N = HID;

    const int tid  = threadIdx.x;
    const int wid  = tid >> 5;
    const int lane = tid & 31;
    const int g    = lane >> 2;
    const int tg   = lane & 3;

    const bf16* B = B0;
    bf16* Cb = Cb0;
    const float* bi = bias0;
    int bx = blockIdx.x;
    if (B1 != nullptr && bx >= ((int)gridDim.x >> 1)) {
        B = B1; Cb = Cb1; bi = bias1; bx -= (int)gridDim.x >> 1;
    }
    const int m0 = blockIdx.y * 128;
    const int n0 = bx * 128;
    const int warpM = (wid >> 2) * 64;
    const int warpN = (wid & 3) * 32;

    const uint32_t sbase = (uint32_t)__cvta_generic_to_shared(smem);

    const int lrow = tid >> 2;          // cp.async row for i=0; i adds 64
    const int lq   = tid & 3;

    uint32_t aOff[4];
#pragma unroll
    for (int mt = 0; mt < 4; mt++)
        aOff[mt] = (uint32_t)((warpM + mt * 16 + (lane & 15)) * 80 + (lane >> 4) * 16);
    uint32_t bOff[2];
#pragma unroll
    for (int np = 0; np < 2; np++)
        bOff[np] = (uint32_t)(10240 +
                   (warpN + np * 16 + (lane & 7) + ((lane & 16) ? 8 : 0)) * 80 +
                   ((lane >> 3) & 1) * 16);

    float acc[4][4][4];
#pragma unroll
    for (int mt = 0; mt < 4; mt++)
#pragma unroll
        for (int nt = 0; nt < 4; nt++)
#pragma unroll
            for (int i = 0; i < 4; i++) acc[mt][nt][i] = 0.f;

    const int nStages = K >> 5;

    auto issue = [&](int buf, int ks) {
        uint32_t sA = sbase + buf * STAGE_BYTES;
        uint32_t sB = sA + 10240;
        int k0 = ks << 5;
#pragma unroll
        for (int i = 0; i < 2; i++) {
            int row = lrow + i * 64;
            int ar = m0 + row; if (ar >= M) ar = M - 1;
            cp16(sA + row * 80 + lq * 16, A + (size_t)ar * K + k0 + lq * 8);
            cp16(sB + row * 80 + lq * 16, B + (size_t)(n0 + row) * K + k0 + lq * 8);
        }
        asm volatile("cp.async.commit_group;");
    };

    issue(0, 0);
    if (nStages > 1) issue(1, 1);
    if (nStages > 2) issue(2, 2);
    if (nStages > 3) issue(3, 3);

    for (int ks = 0; ks < nStages; ks++) {
        int rem = nStages - 1 - ks;
        if (rem >= 3)      asm volatile("cp.async.wait_group 3;");
        else if (rem == 2) asm volatile("cp.async.wait_group 2;");
        else if (rem == 1) asm volatile("cp.async.wait_group 1;");
        else               asm volatile("cp.async.wait_group 0;");
        __syncthreads();

        const uint32_t stage = sbase + (ks % NSTAGE) * STAGE_BYTES;

#pragma unroll
        for (int kk = 0; kk < 32; kk += 16) {
            const uint32_t kb = (kk >> 1) * 4;
            uint32_t a[4][4], b[2][4];
#pragma unroll
            for (int mt = 0; mt < 4; mt++)
                ldsm4(a[mt], stage + aOff[mt] + kb);
#pragma unroll
            for (int np = 0; np < 2; np++)
                ldsm4(b[np], stage + bOff[np] + kb);
#pragma unroll
            for (int mt = 0; mt < 4; mt++) {
                mma_bf16(acc[mt][0], a[mt], &b[0][0]);
                mma_bf16(acc[mt][1], a[mt], &b[0][2]);
                mma_bf16(acc[mt][2], a[mt], &b[1][0]);
                mma_bf16(acc[mt][3], a[mt], &b[1][2]);
            }
        }

        if (ks + 4 < nStages) issue((ks + 4) % NSTAGE, ks + 4);
    }

#pragma unroll
    for (int mt = 0; mt < 4; mt++) {
        int row0 = m0 + warpM + mt * 16 + g;
        int row1 = row0 + 8;
#pragma unroll
        for (int nt = 0; nt < 4; nt++) {
            int col = n0 + warpN + nt * 8 + tg * 2;
            float bx0 = bi[col], bx1 = bi[col + 1];
            float v0 = acc[mt][nt][0] + bx0;
            float v1 = acc[mt][nt][1] + bx1;
            float v2 = acc[mt][nt][2] + bx0;
            float v3 = acc[mt][nt][3] + bx1;
            if (doElu) {
                v0 = v0 > 0.f ? v0 : expm1f(v0);
                v1 = v1 > 0.f ? v1 : expm1f(v1);
                v2 = v2 > 0.f ? v2 : expm1f(v2);
                v3 = v3 > 0.f ? v3 : expm1f(v3);
            }
            if (row0 < M)
                *(__nv_bfloat162*)(Cb + (size_t)row0 * N + col) =
                    __nv_bfloat162(__float2bfloat16(v0), __float2bfloat16(v1));
            if (row1 < M)
                *(__nv_bfloat162*)(Cb + (size_t)row1 * N + col) =
                    __nv_bfloat162(__float2bfloat16(v2), __float2bfloat16(v3));
        }
    }
}

// ---------------- fused edge kernel: 2 warps per node -----------------------
// Per-(node,head) softmax is independent; each warp handles 256 channels
// (4 heads), 8 ch/lane, head = 8-lane group reduced via shfl 1/2/4.
// out = (sum_e ex_e * xl[src_e]) / denom, single pass (softmax linearity).
__global__ void __launch_bounds__(256)
edge_fused(const float* __restrict__ We, const float* __restrict__ att,
           const float* __restrict__ bias)
{
    __shared__ float4 sWe[HID / 4];
    __shared__ float4 sAtt[HID / 4];

    for (int i = threadIdx.x; i < HID / 4; i += blockDim.x) {
        sWe[i]  = ((const float4*)We)[i];
        sAtt[i] = ((const float4*)att)[i];
    }
    __syncthreads();

    const int wid  = threadIdx.x >> 5;
    const int lane = threadIdx.x & 31;
    const int node = blockIdx.x * 4 + (wid >> 1);   // 4 nodes/block
    const int half = wid & 1;                       // channel half [half*256, ...)
    if (node >= NN) return;

    const int ch0 = half * 256 + lane * 8;          // this lane's 8 channels

    int deg = g_cnt[node];
    if (deg > CAP) deg = CAP;
    const int2* bp2 = g_bpack + (size_t)node * CAP;

    // xr slice: 8 channels (one uint4 of bf16)
    float xr[8], we[8], at[8];
    {
        uint4 p = *(const uint4*)(g_xrb + (size_t)node * HID + ch0);
        const __nv_bfloat162* h = (const __nv_bfloat162*)&p;
#pragma unroll
        for (int q = 0; q < 4; q++) {
            float2 f = __bfloat1622float2(h[q]);
            xr[q * 2 + 0] = f.x; xr[q * 2 + 1] = f.y;
        }
        float4 w0 = sWe[ch0 / 4], w1 = sWe[ch0 / 4 + 1];
        float4 t0 = sAtt[ch0 / 4], t1 = sAtt[ch0 / 4 + 1];
        we[0] = w0.x; we[1] = w0.y; we[2] = w0.z; we[3] = w0.w;
        we[4] = w1.x; we[5] = w1.y; we[6] = w1.z; we[7] = w1.w;
        at[0] = t0.x; at[1] = t0.y; at[2] = t0.z; at[3] = t0.w;
        at[4] = t1.x; at[5] = t1.y; at[6] = t1.z; at[7] = t1.w;
    }

    float denom = 0.f;
    float acc[8];
#pragma unroll
    for (int i = 0; i < 8; i++) acc[i] = 0.f;

    int2 eCur = bp2[0];
    uint4 pc = *(const uint4*)(g_xlb + (size_t)eCur.x * HID + ch0);

    for (int j = 0; j < deg; j++) {
        uint4 p = pc;
        const float dv = __int_as_float(eCur.y);
        if (j + 1 < deg) {
            eCur = bp2[j + 1];
            pc = *(const uint4*)(g_xlb + (size_t)eCur.x * HID + ch0);
        }

        float a[8];
        {
            const __nv_bfloat162* h = (const __nv_bfloat162*)&p;
#pragma unroll
            for (int q = 0; q < 4; q++) {
                float2 f = __bfloat1622float2(h[q]);
                a[q * 2 + 0] = f.x; a[q * 2 + 1] = f.y;
            }
        }

        float partial = 0.f;
#pragma unroll
        for (int i = 0; i < 8; i++) {
            float v = a[i] + xr[i] + dv * we[i];
            v = v > 0.f ? v : 0.2f * v;
            partial += v * at[i];
        }
        // reduce across the 8-lane head group
        partial += __shfl_xor_sync(0xffffffffu, partial, 1);
        partial += __shfl_xor_sync(0xffffffffu, partial, 2);
        partial += __shfl_xor_sync(0xffffffffu, partial, 4);
        float ex = __expf(partial);   // softmax shift-invariant; scores O(1)
        denom += ex;
#pragma unroll
        for (int i = 0; i < 8; i++) acc[i] += ex * a[i];
    }

    const float inv = 1.f / denom;      // self-loop => denom > 0

    const float* bp = bias + ch0;
    bf16* hbp = g_hb + (size_t)node * HID + ch0;
#pragma unroll
    for (int i = 0; i < 8; i += 2) {
        float v0 = acc[i] * inv + bp[i];
        float v1 = acc[i + 1] * inv + bp[i + 1];
        v0 = v0 > 0.f ? v0 : expm1f(v0);
        v1 = v1 > 0.f ? v1 : expm1f(v1);
        *(__nv_bfloat162*)(hbp + i) =
            __nv_bfloat162(__float2bfloat16(v0), __float2bfloat16(v1));
    }
}

// ---------------- final: logits = h @ Wa + ba; log_softmax (h = bf16 hb) ----
__global__ void final_kernel(const float* __restrict__ Wa,
                             const float* __restrict__ ba,
                             float* __restrict__ out)
{
    const int row = blockIdx.x * (blockDim.x >> 5) + (threadIdx.x >> 5);
    const int lane = threadIdx.x & 31;
    if (row >= NN) return;

    const bf16* hrow = g_hb + (size_t)row * HID;
    float acc[NCLS];
#pragma unroll
    for (int c = 0; c < NCLS; c++) acc[c] = 0.f;

    for (int k = lane * 2; k < HID; k += 64) {
        float2 hv = __bfloat1622float2(*(const __nv_bfloat162*)(hrow + k));
        const float* w0 = Wa + (size_t)k * NCLS;
        const float* w1 = w0 + NCLS;
#pragma unroll
        for (int c = 0; c < NCLS; c++) acc[c] += hv.x * w0[c] + hv.y * w1[c];
    }
#pragma unroll
    for (int off = 16; off > 0; off >>= 1)
#pragma unroll
        for (int c = 0; c < NCLS; c++)
            acc[c] += __shfl_xor_sync(0xffffffffu, acc[c], off);

    if (lane == 0) {
        float z[NCLS], mx = -1e30f;
#pragma unroll
        for (int c = 0; c < NCLS; c++) { z[c] = acc[c] + ba[c]; mx = fmaxf(mx, z[c]); }
        float s = 0.f;
#pragma unroll
        for (int c = 0; c < NCLS; c++) s += expf(z[c] - mx);
        float lse = mx + logf(s);
#pragma unroll
        for (int c = 0; c < NCLS; c++) out[(size_t)row * NCLS + c] = z[c] - lse;
    }
}

// ---------------- launch ----------------
extern "C" void kernel_launch(void* const* d_in, const int* in_sizes, int n_in,
                              void* d_out, int out_size)
{
    const float* x    = (const float*)d_in[0];
    const int*   ei   = (const int*)d_in[1];      // int32 (JAX x64 disabled)
    const float* dist = (const float*)d_in[2];
    const float* Wb   = (const float*)d_in[3];
    const float* bb   = (const float*)d_in[4];
    const float* Wl   = (const float*)d_in[5];
    const float* bl   = (const float*)d_in[6];
    const float* Wr   = (const float*)d_in[7];
    const float* br   = (const float*)d_in[8];
    const float* We   = (const float*)d_in[9];
    const float* att  = (const float*)d_in[10];
    const float* bc   = (const float*)d_in[11];
    const float* Wa   = (const float*)d_in[12];
    const float* ba   = (const float*)d_in[13];
    float* out = (float*)d_out;

    bf16 *phb, *pxb, *pxlb, *pxrb, *pwbT, *pwlT, *pwrT;
    cudaGetSymbolAddress((void**)&phb,  g_hb);
    cudaGetSymbolAddress((void**)&pxb,  g_xb);
    cudaGetSymbolAddress((void**)&pxlb, g_xlb);
    cudaGetSymbolAddress((void**)&pxrb, g_xrb);
    cudaGetSymbolAddress((void**)&pwbT, g_wbT);
    cudaGetSymbolAddress((void**)&pwlT, g_wlT);
    cudaGetSymbolAddress((void**)&pwrT, g_wrT);

    cudaFuncSetAttribute(bf16gemm, cudaFuncAttributeMaxDynamicSharedMemorySize, GEMM_SMEM);

    // ---- prep; layer-0 dual GEMM stays at ncu capture slot 4 ----
    conv_x_zero<<<(NN * FIN + 255) / 256, 256>>>(x);                        // 1
    transp_bf16_batch7<<<dim3(HID / 32, HID / 32, 7), dim3(32, 8)>>>(Wl, Wr, Wb); // 2
    // fcnn_before: hb = bf16(elu(x @ Wb + bb))                              // 3
    bf16gemm<<<dim3(HID / 128, (NN + 127) / 128), 256, GEMM_SMEM>>>(
        pxb, pwbT, nullptr, bb, nullptr, phb, nullptr, NN, FIN, 1);

    for (int i = 0; i < 3; i++) {
        // fused dual GEMM: xlb = hb @ Wl^T + bl ; xrb = hb @ Wr^T + br      // 4 (i=0)
        bf16gemm<<<dim3(2 * HID / 128, (NN + 127) / 128), 256, GEMM_SMEM>>>(
            phb, pwlT + (size_t)i * HID * HID, pwrT + (size_t)i * HID * HID,
            bl + i * HID, br + i * HID, pxlb, pxrb, NN, HID, 0);
        if (i == 0)
            bucket_kernel<<<(ETOT + 255) / 256, 256>>>(ei, dist);           // 5
        edge_fused<<<(NN + 3) / 4, 256>>>(We + (size_t)i * HID,
                                          att + (size_t)i * HID,
                                          bc + (size_t)i * HID);
    }

    final_kernel<<<(NN + 7) / 8, 256>>>(Wa, ba, out);
}